// round 15
// baseline (speedup 1.0000x reference)
#include <cuda_runtime.h>
#include <math.h>
#include <stdint.h>

#define WSZ    32
#define NH     31
#define NPATCH (NH * NH)   // 961
#define NB     16
#define NC     3
#define IH     512
#define IW     512

#define STRIDE_S 273                    // strip row stride in floats (odd -> conflict-free)
#define SMEM_FLOATS (32 * STRIDE_S + 8 * 512 + 64 + 128)
#define SMEM_BYTES  (SMEM_FLOATS * 4)   // 52,096 B

// ---------------- device globals (no allocations allowed) ----------------
__device__ float gDT[16 * 32];            // gDT[j*32+i] = D[i][j], j < 16 (symmetry half)
__device__ float gW[64];                  // diagonal weight table W[s], s = i+k in [0,62]
__device__ float gGradeC[NB * NPATCH * 4]; // per-channel partial grades, stride 4 (c=0..2)
__device__ int   gSel[NB * 4];            // per batch: [minmin, maxmax, minmin1, maxmax1]

// ---------------- packed f32x2 helpers (sm_103a) ----------------
__device__ __forceinline__ uint64_t pack2(float v) {
    uint64_t r; asm("mov.b64 %0, {%1, %1};" : "=l"(r) : "f"(v)); return r;
}
__device__ __forceinline__ void unpack2(float& lo, float& hi, uint64_t v) {
    asm("mov.b64 {%0, %1}, %2;" : "=f"(lo), "=f"(hi) : "l"(v));
}
__device__ __forceinline__ void fma2(uint64_t& a, uint64_t x, uint64_t y) {
    asm("fma.rn.f32x2 %0, %1, %2, %0;" : "+l"(a) : "l"(x), "l"(y));
}
// "memory" clobber (not volatile): orders this shared-load against the
// memory-clobbering bar.sync (fixes the R13 hoist hazard) while leaving the
// compiler free to schedule within a barrier-delimited phase.
__device__ __forceinline__ void lds_v2u64(uint64_t& w0, uint64_t& w1, uint32_t addr) {
    asm("ld.shared.v2.u64 {%0, %1}, [%2];"
        : "=l"(w0), "=l"(w1) : "r"(addr) : "memory");
}
__device__ __forceinline__ void barsync128(int id) {
    asm volatile("bar.sync %0, 128;" :: "r"(id) : "memory");
}

// ---------------- init: DCT matrix + grade-weight table (fully parallel) ----------------
__global__ void init_kernel() {
    __shared__ float sft[6];
    const int tid = threadIdx.x;         // 512 threads
    const int i = tid >> 4, j = tid & 15;
    double scale = (i == 0) ? sqrt(1.0 / 32.0) : sqrt(2.0 / 32.0);
    double v = scale * cos((((double)j + 0.5) * 3.141592653589793) * (double)i / 32.0);
    gDT[j * 32 + i] = (float)v;

    const double q = (double)WSZ * 2.0 / 6.0;         // 64/6 in IEEE double, like numpy
    if (tid < 6) {
        double st = q * (double)tid;
        double en = q * (double)(tid + 1);
        float ft = 0.0f;
        for (int s = 0; s <= 62; s++) {
            bool in = !((double)s > en || (double)s < st);
            if (in) ft += (float)((s <= 31) ? (s + 1) : (63 - s));
        }
        sft[tid] = ft;
    }
    __syncthreads();
    if (tid < 63) {
        float w = 0.0f;
        #pragma unroll
        for (int g = 0; g < 6; g++) {
            double st = q * (double)g;
            double en = q * (double)(g + 1);
            bool in = !((double)tid > en || (double)tid < st);
            if (in) w += ((float)(1 << g)) / sft[g];
        }
        gW[tid] = w;
    }
    if (tid == 63) gW[63] = 0.0f;
}

// ---------------- grade: (b, hr, c, half-strip) per block; 2 patches in flight ----------------
// 256 threads = two decoupled 128-thread groups (named barriers), one patch each.
// Per thread: ks {k1, k1+16}; packed f32x2 accumulators; D in registers.
// (R9 structure: in-loop warp reduction — the proven 152.7us configuration.)
__global__ __launch_bounds__(256) void grade_kernel(const float* __restrict__ x) {
    extern __shared__ __align__(16) float sm[];
    float* strip = sm;                        // [32][273]
    float* U1b   = sm + 32 * STRIDE_S;        // [2][16][32]
    float* V1b   = U1b + 1024;
    float* U2b   = V1b + 1024;
    float* V2b   = U2b + 1024;
    float* Wt    = V2b + 1024;                // [64]
    float* gpart = Wt + 64;                   // [8][16]

    const int idx0 = blockIdx.x;              // (((b*31 + hr)*3 + c)*2 + hs)
    const int hs   = idx0 & 1;
    const int bhc  = idx0 >> 1;
    const int c    = bhc % 3;
    const int bh   = bhc / 3;
    const int hr   = bh % NH;
    const int b    = bh / NH;
    const int tid  = threadIdx.x;
    const int lane = tid & 31;
    const int sub  = tid >> 7;                // 128-thread group id
    const int st   = tid & 127;
    const int sw   = st >> 5;                 // warp-in-group 0..3
    const int k1   = st & 15;                 // this thread's ks: k1, k1+16
    const int q    = st >> 4;                 // row/k quad 0..7

    const int colbase = hs ? 256 : 0;
    const int ncols4  = hs ? 64 : 68;
    const int npat    = hs ? 15 : 16;

    // D half-matrix columns for k1 and k1+16 (reused by stage 2: i1 = k1)
    float dregA[16], dregB[16];
    #pragma unroll
    for (int jp = 0; jp < 16; jp++) {
        dregA[jp] = __ldg(&gDT[jp * 32 + k1]);
        dregB[jp] = __ldg(&gDT[jp * 32 + k1 + 16]);
    }
    if (tid < 64) Wt[tid] = gW[tid];

    // load half-strip (both groups cooperate)
    const float* xs = x + (((size_t)(b * NC + c)) * IH + hr * 16) * IW + colbase;
    const int nf4 = ncols4 * 32;
    for (int idx = tid; idx < nf4; idx += 256) {
        int r  = idx / ncols4;
        int qq = idx - r * ncols4;
        float4 g4 = *(const float4*)(xs + (size_t)r * IW + qq * 4);
        float* row = strip + r * STRIDE_S + qq * 4;
        row[0] = g4.x; row[1] = g4.y; row[2] = g4.z; row[3] = g4.w;
    }
    __syncthreads();

    float* U1s = U1b + sub * 512;
    float* V1s = V1b + sub * 512;
    float* U2s = U2b + sub * 512;
    float* V2s = V2b + sub * 512;
    const uint32_t u1a = (uint32_t)__cvta_generic_to_shared(U1s);
    const uint32_t v1a = (uint32_t)__cvta_generic_to_shared(V1s);
    const uint32_t u2a = (uint32_t)__cvta_generic_to_shared(U2s);
    const uint32_t v2a = (uint32_t)__cvta_generic_to_shared(V2s);
    const uint32_t wb1 = (k1 & 1) ? v1a : u1a;    // parity(k1) == parity(k1+16)
    const uint32_t wb2 = (k1 & 1) ? v2a : u2a;

    // rho': pos 4q+{0,1,2,3} = rows {2q, 2q+1, 31-2q, 30-2q}
    const int rho = (lane < 16) ? (2 * lane - (lane & 1))
                                : ((lane & 1) ? (64 - 2 * lane) : (63 - 2 * lane));
    const int bid = 1 + sub;                  // named barrier id per group

    #define FOLD(pp) do {                                                   \
        const float* rowp = strip + lane * STRIDE_S + (pp) * 16;            \
        _Pragma("unroll")                                                   \
        for (int s = 0; s < 4; s++) {                                       \
            int jp = sw + 4 * s;                                            \
            float a  = rowp[jp];                                            \
            float bb = rowp[31 - jp];                                       \
            U1s[jp * 32 + rho] = a + bb;                                    \
            V1s[jp * 32 + rho] = a - bb;                                    \
        }                                                                   \
    } while (0)

    if (sub < npat) FOLD(sub);                // pp = 2*0 + sub
    barsync128(bid);

    for (int it = 0; it < 8; it++) {
        const int pp = 2 * it + sub;
        const bool valid = pp < npat;

        // ---- stage 1 + fused fold-2 ----
        if (valid) {
            uint64_t A01a = 0, A32a = 0, A01b = 0, A32b = 0;
            #pragma unroll
            for (int jp = 0; jp < 16; jp++) {
                uint64_t w01, w32;
                lds_v2u64(w01, w32, wb1 + (uint32_t)(jp * 32 + 4 * q) * 4u);
                uint64_t dd1 = pack2(dregA[jp]);
                uint64_t dd2 = pack2(dregB[jp]);
                fma2(A01a, w01, dd1); fma2(A32a, w32, dd1);
                fma2(A01b, w01, dd2); fma2(A32b, w32, dd2);
            }
            float o0, o1, o31, o30;
            unpack2(o0, o1, A01a); unpack2(o31, o30, A32a);
            U2s[(2 * q) * 32 + k1]          = o0 + o31;
            V2s[(2 * q) * 32 + k1]          = o0 - o31;
            U2s[(2 * q + 1) * 32 + k1]      = o1 + o30;
            V2s[(2 * q + 1) * 32 + k1]      = o1 - o30;
            unpack2(o0, o1, A01b); unpack2(o31, o30, A32b);
            U2s[(2 * q) * 32 + k1 + 16]     = o0 + o31;
            V2s[(2 * q) * 32 + k1 + 16]     = o0 - o31;
            U2s[(2 * q + 1) * 32 + k1 + 16] = o1 + o30;
            V2s[(2 * q + 1) * 32 + k1 + 16] = o1 - o30;
        }
        barsync128(bid);

        // ---- stage 2 + grade, overlapped with fold of next patch ----
        if (valid) {
            uint64_t P0a = 0, P1a = 0, P0b = 0, P1b = 0;
            #pragma unroll
            for (int rp = 0; rp < 16; rp++) {
                uint64_t w01, w23;
                lds_v2u64(w01, w23, wb2 + (uint32_t)(rp * 32 + 4 * q) * 4u);
                uint64_t dd1 = pack2(dregA[rp]);
                uint64_t dd2 = pack2(dregB[rp]);
                fma2(P0a, w01, dd1); fma2(P1a, w23, dd1);
                fma2(P0b, w01, dd2); fma2(P1b, w23, dd2);
            }
            float x0, x1, x2, x3, y0, y1, y2, y3;
            unpack2(x0, x1, P0a); unpack2(x2, x3, P1a);
            unpack2(y0, y1, P0b); unpack2(y2, y3, P1b);
            const int k0 = 4 * q;
            float g;
            g  = __logf(fabsf(x0) + 1.0f) * Wt[k1 + k0 + 0];
            g += __logf(fabsf(x1) + 1.0f) * Wt[k1 + k0 + 1];
            g += __logf(fabsf(x2) + 1.0f) * Wt[k1 + k0 + 2];
            g += __logf(fabsf(x3) + 1.0f) * Wt[k1 + k0 + 3];
            g += __logf(fabsf(y0) + 1.0f) * Wt[k1 + 16 + k0 + 0];
            g += __logf(fabsf(y1) + 1.0f) * Wt[k1 + 16 + k0 + 1];
            g += __logf(fabsf(y2) + 1.0f) * Wt[k1 + 16 + k0 + 2];
            g += __logf(fabsf(y3) + 1.0f) * Wt[k1 + 16 + k0 + 3];
            #pragma unroll
            for (int o = 16; o > 0; o >>= 1) g += __shfl_down_sync(0xFFFFFFFFu, g, o);
            if (lane == 0) gpart[(sub * 4 + sw) * 16 + it] = g;
        }
        const int ppn = 2 * (it + 1) + sub;
        if (it < 7 && ppn < npat) FOLD(ppn);
        barsync128(bid);
    }
    #undef FOLD

    __syncthreads();
    // deferred 4-warp sums -> gGradeC (patch pp: sub = pp&1, it = pp>>1)
    if (tid < npat) {
        const int su = tid & 1, itp = tid >> 1;
        float s = 0.f;
        #pragma unroll
        for (int w = 0; w < 4; w++) s += gpart[(su * 4 + w) * 16 + itp];
        int pl = b * NPATCH + hr * NH + (hs ? 16 : 0) + tid;
        gGradeC[pl * 4 + c] = s;
    }
}

// ---------------- selection: stable-argsort-compatible top2/bottom2 ----------------
__global__ void select_kernel() {
    __shared__ unsigned long long smin[256][2];
    __shared__ unsigned long long smax[256][2];
    const int b   = blockIdx.x;
    const int tid = threadIdx.x;
    const float* gr = &gGradeC[b * NPATCH * 4];

    unsigned long long mn1 = ~0ull, mn2 = ~0ull, mx1 = 0ull, mx2 = 0ull;
    for (int l = tid; l < NPATCH; l += 256) {
        float val = gr[l * 4 + 0] + gr[l * 4 + 1] + gr[l * 4 + 2];
        unsigned int ub = __float_as_uint(val);
        ub = (ub & 0x80000000u) ? ~ub : (ub | 0x80000000u);   // order-preserving map
        unsigned long long key = ((unsigned long long)ub << 32) | (unsigned)l;
        if (key < mn1) { mn2 = mn1; mn1 = key; } else if (key < mn2) { mn2 = key; }
        if (key > mx1) { mx2 = mx1; mx1 = key; } else if (key > mx2) { mx2 = key; }
    }
    smin[tid][0] = mn1; smin[tid][1] = mn2;
    smax[tid][0] = mx1; smax[tid][1] = mx2;
    __syncthreads();
    for (int s = 128; s > 0; s >>= 1) {
        if (tid < s) {
            unsigned long long a1 = smin[tid][0], a2 = smin[tid][1];
            unsigned long long b1 = smin[tid + s][0], b2 = smin[tid + s][1];
            smin[tid][0] = min(a1, b1);
            smin[tid][1] = min(max(a1, b1), min(a2, b2));
            a1 = smax[tid][0]; a2 = smax[tid][1];
            b1 = smax[tid + s][0]; b2 = smax[tid + s][1];
            smax[tid][0] = max(a1, b1);
            smax[tid][1] = max(min(a1, b1), max(a2, b2));
        }
        __syncthreads();
    }
    if (tid == 0) {
        gSel[b * 4 + 0] = (int)(smin[0][0] & 0xFFFFFFFFull);  // minmin  = idx[0]
        gSel[b * 4 + 1] = (int)(smax[0][0] & 0xFFFFFFFFull);  // maxmax  = idx[-1]
        gSel[b * 4 + 2] = (int)(smin[0][1] & 0xFFFFFFFFull);  // minmin1 = idx[1]
        gSel[b * 4 + 3] = (int)(smax[0][1] & 0xFFFFFFFFull);  // maxmax1 = idx[-2]
    }
}

// ---------------- gather: level_y == patch (orthogonal DCT round-trip) ----------------
__global__ void gather_kernel(const float* __restrict__ x, float* __restrict__ out) {
    const int id  = blockIdx.x;            // sel*48 + b*3 + c
    const int sel = id / 48;
    const int bc  = id - sel * 48;
    const int b   = bc / 3;
    const int c   = bc - b * 3;
    const int l   = gSel[b * 4 + sel];
    const int hr  = l / NH;
    const int wc  = l - hr * NH;

    const float4* src = (const float4*)(x + (((size_t)(b * NC + c)) * IH + hr * 16) * IW + wc * 16);
    float4* dst = (float4*)(out + (size_t)id * 1024);
    const int t  = threadIdx.x;            // 256 threads, one float4 each
    const int r  = t >> 3;
    const int jq = t & 7;
    dst[r * 8 + jq] = src[r * (IW / 4) + jq];
}

// ---------------- launch ----------------
extern "C" void kernel_launch(void* const* d_in, const int* in_sizes, int n_in,
                              void* d_out, int out_size) {
    const float* x = (const float*)d_in[0];
    float* out = (float*)d_out;
    cudaFuncSetAttribute(grade_kernel, cudaFuncAttributeMaxDynamicSharedMemorySize, SMEM_BYTES);
    init_kernel<<<1, 512>>>();
    grade_kernel<<<NB * NH * NC * 2, 256, SMEM_BYTES>>>(x);
    select_kernel<<<NB, 256>>>();
    gather_kernel<<<4 * NB * NC, 256>>>(x, out);
}

// round 17
// speedup vs baseline: 1.6080x; 1.6080x over previous
#include <cuda_runtime.h>
#include <math.h>
#include <stdint.h>

#define WSZ    32
#define NH     31
#define NPATCH (NH * NH)   // 961
#define NB     16
#define NC     3
#define IH     512
#define IW     512

#define STRIDE_S 273                    // strip row stride in floats (odd -> conflict-free)
#define SMEM_FLOATS (32 * STRIDE_S + 8 * 512 + 64 + 128)
#define SMEM_BYTES  (SMEM_FLOATS * 4)   // 52,096 B

// ---------------- device globals (no allocations allowed) ----------------
__device__ float gDT[16 * 32];            // gDT[j*32+i] = D[i][j], j < 16 (symmetry half)
__device__ float gW[64];                  // diagonal weight table W[s], s = i+k in [0,62]
__device__ float gGradeC[NB * NPATCH * 4]; // per-channel partial grades, stride 4 (c=0..2)
__device__ int   gSel[NB * 4];            // per batch: [minmin, maxmax, minmin1, maxmax1]

// ---------------- packed f32x2 helpers (sm_103a) ----------------
__device__ __forceinline__ uint64_t pack2(float v) {
    uint64_t r; asm("mov.b64 %0, {%1, %1};" : "=l"(r) : "f"(v)); return r;
}
__device__ __forceinline__ void unpack2(float& lo, float& hi, uint64_t v) {
    asm("mov.b64 {%0, %1}, %2;" : "=f"(lo), "=f"(hi) : "l"(v));
}
__device__ __forceinline__ void fma2(uint64_t& a, uint64_t x, uint64_t y) {
    asm("fma.rn.f32x2 %0, %1, %2, %0;" : "+l"(a) : "l"(x), "l"(y));
}
__device__ __forceinline__ void lds_v2u64(uint64_t& w0, uint64_t& w1, uint32_t addr) {
    asm("ld.shared.v2.u64 {%0, %1}, [%2];" : "=l"(w0), "=l"(w1) : "r"(addr));
}
__device__ __forceinline__ void barsync128(int id) {
    asm volatile("bar.sync %0, 128;" :: "r"(id) : "memory");
}

// ---------------- init: DCT matrix + grade-weight table (fully parallel) ----------------
__global__ void init_kernel() {
    __shared__ float sft[6];
    const int tid = threadIdx.x;         // 512 threads
    const int i = tid >> 4, j = tid & 15;
    double scale = (i == 0) ? sqrt(1.0 / 32.0) : sqrt(2.0 / 32.0);
    double v = scale * cos((((double)j + 0.5) * 3.141592653589793) * (double)i / 32.0);
    gDT[j * 32 + i] = (float)v;

    const double q = (double)WSZ * 2.0 / 6.0;         // 64/6 in IEEE double, like numpy
    if (tid < 6) {
        double st = q * (double)tid;
        double en = q * (double)(tid + 1);
        float ft = 0.0f;
        for (int s = 0; s <= 62; s++) {
            bool in = !((double)s > en || (double)s < st);
            if (in) ft += (float)((s <= 31) ? (s + 1) : (63 - s));
        }
        sft[tid] = ft;
    }
    __syncthreads();
    if (tid < 63) {
        float w = 0.0f;
        #pragma unroll
        for (int g = 0; g < 6; g++) {
            double st = q * (double)g;
            double en = q * (double)(g + 1);
            bool in = !((double)tid > en || (double)tid < st);
            if (in) w += ((float)(1 << g)) / sft[g];
        }
        gW[tid] = w;
    }
    if (tid == 63) gW[63] = 0.0f;
}

// ---------------- grade: (b, hr, c, half-strip) per block; 2 patches in flight ----------------
// 256 threads = two decoupled 128-thread groups (named barriers), one patch each.
// Per thread: ks {k1, k1+16}; packed f32x2 accumulators over row/k pairs.
__global__ __launch_bounds__(256) void grade_kernel(const float* __restrict__ x) {
    extern __shared__ __align__(16) float sm[];
    float* strip = sm;                        // [32][273]
    float* U1b   = sm + 32 * STRIDE_S;        // [2][16][32]
    float* V1b   = U1b + 1024;
    float* U2b   = V1b + 1024;
    float* V2b   = U2b + 1024;
    float* Wt    = V2b + 1024;                // [64]
    float* gpart = Wt + 64;                   // [8][16]

    const int idx0 = blockIdx.x;              // (((b*31 + hr)*3 + c)*2 + hs)
    const int hs   = idx0 & 1;
    const int bhc  = idx0 >> 1;
    const int c    = bhc % 3;
    const int bh   = bhc / 3;
    const int hr   = bh % NH;
    const int b    = bh / NH;
    const int tid  = threadIdx.x;
    const int lane = tid & 31;
    const int sub  = tid >> 7;                // 128-thread group id
    const int st   = tid & 127;
    const int sw   = st >> 5;                 // warp-in-group 0..3
    const int k1   = st & 15;                 // this thread's ks: k1, k1+16
    const int q    = st >> 4;                 // row/k quad 0..7

    const int colbase = hs ? 256 : 0;
    const int ncols4  = hs ? 64 : 68;
    const int npat    = hs ? 15 : 16;

    // D half-matrix columns for k1 and k1+16 (reused by stage 2: i1 = k1)
    float dregA[16], dregB[16];
    #pragma unroll
    for (int jp = 0; jp < 16; jp++) {
        dregA[jp] = __ldg(&gDT[jp * 32 + k1]);
        dregB[jp] = __ldg(&gDT[jp * 32 + k1 + 16]);
    }
    if (tid < 64) Wt[tid] = gW[tid];

    // load half-strip (both groups cooperate)
    const float* xs = x + (((size_t)(b * NC + c)) * IH + hr * 16) * IW + colbase;
    const int nf4 = ncols4 * 32;
    for (int idx = tid; idx < nf4; idx += 256) {
        int r  = idx / ncols4;
        int qq = idx - r * ncols4;
        float4 g4 = *(const float4*)(xs + (size_t)r * IW + qq * 4);
        float* row = strip + r * STRIDE_S + qq * 4;
        row[0] = g4.x; row[1] = g4.y; row[2] = g4.z; row[3] = g4.w;
    }
    __syncthreads();

    float* U1s = U1b + sub * 512;
    float* V1s = V1b + sub * 512;
    float* U2s = U2b + sub * 512;
    float* V2s = V2b + sub * 512;
    const uint32_t u1a = (uint32_t)__cvta_generic_to_shared(U1s);
    const uint32_t v1a = (uint32_t)__cvta_generic_to_shared(V1s);
    const uint32_t u2a = (uint32_t)__cvta_generic_to_shared(U2s);
    const uint32_t v2a = (uint32_t)__cvta_generic_to_shared(V2s);
    const uint32_t wb1 = (k1 & 1) ? v1a : u1a;    // parity(k1) == parity(k1+16)
    const uint32_t wb2 = (k1 & 1) ? v2a : u2a;

    // rho': pos 4q+{0,1,2,3} = rows {2q, 2q+1, 31-2q, 30-2q}
    const int rho = (lane < 16) ? (2 * lane - (lane & 1))
                                : ((lane & 1) ? (64 - 2 * lane) : (63 - 2 * lane));
    const int bid = 1 + sub;                  // named barrier id per group

    #define FOLD(pp) do {                                                   \
        const float* rowp = strip + lane * STRIDE_S + (pp) * 16;            \
        _Pragma("unroll")                                                   \
        for (int s = 0; s < 4; s++) {                                       \
            int jp = sw + 4 * s;                                            \
            float a  = rowp[jp];                                            \
            float bb = rowp[31 - jp];                                       \
            U1s[jp * 32 + rho] = a + bb;                                    \
            V1s[jp * 32 + rho] = a - bb;                                    \
        }                                                                   \
    } while (0)

    if (sub < npat) FOLD(sub);                // pp = 2*0 + sub
    barsync128(bid);

    for (int it = 0; it < 8; it++) {
        const int pp = 2 * it + sub;
        const bool valid = pp < npat;

        // ---- stage 1 + fused fold-2 ----
        if (valid) {
            uint64_t A01a = 0, A32a = 0, A01b = 0, A32b = 0;
            #pragma unroll
            for (int jp = 0; jp < 16; jp++) {
                uint64_t w01, w32;
                lds_v2u64(w01, w32, wb1 + (uint32_t)(jp * 32 + 4 * q) * 4u);
                uint64_t dd1 = pack2(dregA[jp]);
                uint64_t dd2 = pack2(dregB[jp]);
                fma2(A01a, w01, dd1); fma2(A32a, w32, dd1);
                fma2(A01b, w01, dd2); fma2(A32b, w32, dd2);
            }
            float o0, o1, o31, o30;
            unpack2(o0, o1, A01a); unpack2(o31, o30, A32a);
            U2s[(2 * q) * 32 + k1]          = o0 + o31;
            V2s[(2 * q) * 32 + k1]          = o0 - o31;
            U2s[(2 * q + 1) * 32 + k1]      = o1 + o30;
            V2s[(2 * q + 1) * 32 + k1]      = o1 - o30;
            unpack2(o0, o1, A01b); unpack2(o31, o30, A32b);
            U2s[(2 * q) * 32 + k1 + 16]     = o0 + o31;
            V2s[(2 * q) * 32 + k1 + 16]     = o0 - o31;
            U2s[(2 * q + 1) * 32 + k1 + 16] = o1 + o30;
            V2s[(2 * q + 1) * 32 + k1 + 16] = o1 - o30;
        }
        barsync128(bid);

        // ---- stage 2 + grade, overlapped with fold of next patch ----
        if (valid) {
            uint64_t P0a = 0, P1a = 0, P0b = 0, P1b = 0;
            #pragma unroll
            for (int rp = 0; rp < 16; rp++) {
                uint64_t w01, w23;
                lds_v2u64(w01, w23, wb2 + (uint32_t)(rp * 32 + 4 * q) * 4u);
                uint64_t dd1 = pack2(dregA[rp]);
                uint64_t dd2 = pack2(dregB[rp]);
                fma2(P0a, w01, dd1); fma2(P1a, w23, dd1);
                fma2(P0b, w01, dd2); fma2(P1b, w23, dd2);
            }
            float x0, x1, x2, x3, y0, y1, y2, y3;
            unpack2(x0, x1, P0a); unpack2(x2, x3, P1a);
            unpack2(y0, y1, P0b); unpack2(y2, y3, P1b);
            const int k0 = 4 * q;
            float g;
            g  = __logf(fabsf(x0) + 1.0f) * Wt[k1 + k0 + 0];
            g += __logf(fabsf(x1) + 1.0f) * Wt[k1 + k0 + 1];
            g += __logf(fabsf(x2) + 1.0f) * Wt[k1 + k0 + 2];
            g += __logf(fabsf(x3) + 1.0f) * Wt[k1 + k0 + 3];
            g += __logf(fabsf(y0) + 1.0f) * Wt[k1 + 16 + k0 + 0];
            g += __logf(fabsf(y1) + 1.0f) * Wt[k1 + 16 + k0 + 1];
            g += __logf(fabsf(y2) + 1.0f) * Wt[k1 + 16 + k0 + 2];
            g += __logf(fabsf(y3) + 1.0f) * Wt[k1 + 16 + k0 + 3];
            #pragma unroll
            for (int o = 16; o > 0; o >>= 1) g += __shfl_down_sync(0xFFFFFFFFu, g, o);
            if (lane == 0) gpart[(sub * 4 + sw) * 16 + it] = g;
        }
        const int ppn = 2 * (it + 1) + sub;
        if (it < 7 && ppn < npat) FOLD(ppn);
        barsync128(bid);
    }
    #undef FOLD

    __syncthreads();
    // deferred 4-warp sums -> gGradeC (patch pp: sub = pp&1, it = pp>>1)
    if (tid < npat) {
        const int su = tid & 1, itp = tid >> 1;
        float s = 0.f;
        #pragma unroll
        for (int w = 0; w < 4; w++) s += gpart[(su * 4 + w) * 16 + itp];
        int pl = b * NPATCH + hr * NH + (hs ? 16 : 0) + tid;
        gGradeC[pl * 4 + c] = s;
    }
}

// ---------------- selection: stable-argsort-compatible top2/bottom2 ----------------
__global__ void select_kernel() {
    __shared__ unsigned long long smin[256][2];
    __shared__ unsigned long long smax[256][2];
    const int b   = blockIdx.x;
    const int tid = threadIdx.x;
    const float* gr = &gGradeC[b * NPATCH * 4];

    unsigned long long mn1 = ~0ull, mn2 = ~0ull, mx1 = 0ull, mx2 = 0ull;
    for (int l = tid; l < NPATCH; l += 256) {
        float val = gr[l * 4 + 0] + gr[l * 4 + 1] + gr[l * 4 + 2];
        unsigned int ub = __float_as_uint(val);
        ub = (ub & 0x80000000u) ? ~ub : (ub | 0x80000000u);   // order-preserving map
        unsigned long long key = ((unsigned long long)ub << 32) | (unsigned)l;
        if (key < mn1) { mn2 = mn1; mn1 = key; } else if (key < mn2) { mn2 = key; }
        if (key > mx1) { mx2 = mx1; mx1 = key; } else if (key > mx2) { mx2 = key; }
    }
    smin[tid][0] = mn1; smin[tid][1] = mn2;
    smax[tid][0] = mx1; smax[tid][1] = mx2;
    __syncthreads();
    for (int s = 128; s > 0; s >>= 1) {
        if (tid < s) {
            unsigned long long a1 = smin[tid][0], a2 = smin[tid][1];
            unsigned long long b1 = smin[tid + s][0], b2 = smin[tid + s][1];
            smin[tid][0] = min(a1, b1);
            smin[tid][1] = min(max(a1, b1), min(a2, b2));
            a1 = smax[tid][0]; a2 = smax[tid][1];
            b1 = smax[tid + s][0]; b2 = smax[tid + s][1];
            smax[tid][0] = max(a1, b1);
            smax[tid][1] = max(min(a1, b1), max(a2, b2));
        }
        __syncthreads();
    }
    if (tid == 0) {
        gSel[b * 4 + 0] = (int)(smin[0][0] & 0xFFFFFFFFull);  // minmin  = idx[0]
        gSel[b * 4 + 1] = (int)(smax[0][0] & 0xFFFFFFFFull);  // maxmax  = idx[-1]
        gSel[b * 4 + 2] = (int)(smin[0][1] & 0xFFFFFFFFull);  // minmin1 = idx[1]
        gSel[b * 4 + 3] = (int)(smax[0][1] & 0xFFFFFFFFull);  // maxmax1 = idx[-2]
    }
}

// ---------------- gather: level_y == patch (orthogonal DCT round-trip) ----------------
__global__ void gather_kernel(const float* __restrict__ x, float* __restrict__ out) {
    const int id  = blockIdx.x;            // sel*48 + b*3 + c
    const int sel = id / 48;
    const int bc  = id - sel * 48;
    const int b   = bc / 3;
    const int c   = bc - b * 3;
    const int l   = gSel[b * 4 + sel];
    const int hr  = l / NH;
    const int wc  = l - hr * NH;

    const float4* src = (const float4*)(x + (((size_t)(b * NC + c)) * IH + hr * 16) * IW + wc * 16);
    float4* dst = (float4*)(out + (size_t)id * 1024);
    const int t  = threadIdx.x;            // 256 threads, one float4 each
    const int r  = t >> 3;
    const int jq = t & 7;
    dst[r * 8 + jq] = src[r * (IW / 4) + jq];
}

// ---------------- launch ----------------
extern "C" void kernel_launch(void* const* d_in, const int* in_sizes, int n_in,
                              void* d_out, int out_size) {
    const float* x = (const float*)d_in[0];
    float* out = (float*)d_out;
    cudaFuncSetAttribute(grade_kernel, cudaFuncAttributeMaxDynamicSharedMemorySize, SMEM_BYTES);
    init_kernel<<<1, 512>>>();
    grade_kernel<<<NB * NH * NC * 2, 256, SMEM_BYTES>>>(x);
    select_kernel<<<NB, 256>>>();
    gather_kernel<<<4 * NB * NC, 256>>>(x, out);
}